// round 1
// baseline (speedup 1.0000x reference)
#include <cuda_runtime.h>
#include <math.h>

#define Bk 8
#define Sk 128
#define Dk 300
#define Ek 50
#define DEPk 50

// Scratch (no allocations allowed)
__device__ float g_Abar[Bk * Sk * Sk];          // (B,S,S)
__device__ float g_Ax[Bk * Sk * Dk];            // (B,S,D)
__device__ float g_Wt[Dk * Dk];                 // W transposed: Wt[d*D+i] = W[i*D+d]
__device__ float g_pa[Bk * Sk * DEPk];
__device__ float g_pb[Bk * Sk * DEPk];

// ---------------------------------------------------------------------------
// K1: Abar[b,s,t] = (1/E) * ( sum_e wps[b,s,t,e] + sum_e sl[b,e,s,t] )
// grid (S, B), 128 threads (t)
// ---------------------------------------------------------------------------
__global__ __launch_bounds__(128) void k_abar(const float* __restrict__ wps,
                                              const float* __restrict__ sl) {
    const int t = threadIdx.x;
    const int s = blockIdx.x;
    const int b = blockIdx.y;

    // wps row: contiguous E=50 floats, 200B-aligned -> float2
    const float2* w2 = reinterpret_cast<const float2*>(
        wps + ((size_t)((b * Sk + s) * Sk) + t) * Ek);
    float s1 = 0.f;
#pragma unroll
    for (int e = 0; e < Ek / 2; ++e) {
        float2 v = w2[e];
        s1 += v.x + v.y;
    }

    // self_loop: stride S*S over e, coalesced across t
    const float* sp = sl + (size_t)b * Ek * Sk * Sk + s * Sk + t;
    float s2 = 0.f;
#pragma unroll
    for (int e = 0; e < Ek; ++e) s2 += sp[(size_t)e * Sk * Sk];

    g_Abar[(b * Sk + s) * Sk + t] = (s1 + s2) * (1.0f / Ek);
}

// ---------------------------------------------------------------------------
// K2: Ax[b,s,d] = sum_t Abar[b,s,t] * x[b,t,d]
// grid (S/8, B), 128 threads; each thread owns d = tid, tid+128, tid+256
// ---------------------------------------------------------------------------
#define ST2 8
__global__ __launch_bounds__(128) void k_ax(const float* __restrict__ x) {
    __shared__ float Ab[ST2][Sk];
    const int tid = threadIdx.x;
    const int s0 = blockIdx.x * ST2;
    const int b = blockIdx.y;

#pragma unroll
    for (int r = 0; r < ST2; ++r)
        Ab[r][tid] = g_Abar[(b * Sk + s0 + r) * Sk + tid];
    __syncthreads();

    const int d0 = tid, d1 = tid + 128, d2 = tid + 256;
    const bool v2 = (d2 < Dk);

    float acc[ST2][3];
#pragma unroll
    for (int r = 0; r < ST2; ++r)
        acc[r][0] = acc[r][1] = acc[r][2] = 0.f;

    for (int t = 0; t < Sk; ++t) {
        const float* xr = x + (size_t)(b * Sk + t) * Dk;
        float x0 = xr[d0];
        float x1 = xr[d1];
        float x2 = v2 ? xr[d2] : 0.f;
#pragma unroll
        for (int r = 0; r < ST2; ++r) {
            float a = Ab[r][t];
            acc[r][0] = fmaf(a, x0, acc[r][0]);
            acc[r][1] = fmaf(a, x1, acc[r][1]);
            acc[r][2] = fmaf(a, x2, acc[r][2]);
        }
    }
#pragma unroll
    for (int r = 0; r < ST2; ++r) {
        float* o = g_Ax + (size_t)(b * Sk + s0 + r) * Dk;
        o[d0] = acc[r][0];
        o[d1] = acc[r][1];
        if (v2) o[d2] = acc[r][2];
    }
}

// ---------------------------------------------------------------------------
// K2b: transpose W (so the g-GEMM loads coalesce over i)
// grid (D), 320 threads
// ---------------------------------------------------------------------------
__global__ __launch_bounds__(320) void k_wt(const float* __restrict__ W) {
    const int d = blockIdx.x;
    const int i = threadIdx.x;
    if (i < Dk) g_Wt[d * Dk + i] = W[i * Dk + d];
}

// ---------------------------------------------------------------------------
// K3: g = Ax @ W^T + b, LayerNorm(ddof=1), ReLU -> node
// grid (S/8, B), 320 threads (i = tid, i<300 active)
// ---------------------------------------------------------------------------
#define ST3 8
__global__ __launch_bounds__(320) void k_gemm_ln(const float* __restrict__ Wb,
                                                const float* __restrict__ lna,
                                                const float* __restrict__ lnb,
                                                float* __restrict__ node) {
    __shared__ float Axs[ST3][Dk];
    __shared__ float Gs[ST3][Dk];
    __shared__ float mean_s[ST3], inv_s[ST3];

    const int tid = threadIdx.x;
    const int s0 = blockIdx.x * ST3;
    const int b = blockIdx.y;

    for (int idx = tid; idx < ST3 * Dk; idx += blockDim.x) {
        int r = idx / Dk, c = idx - r * Dk;
        Axs[r][c] = g_Ax[(size_t)(b * Sk + s0 + r) * Dk + c];
    }
    __syncthreads();

    const int i = tid;
    if (i < Dk) {
        float acc[ST3];
#pragma unroll
        for (int r = 0; r < ST3; ++r) acc[r] = 0.f;
        for (int d = 0; d < Dk; ++d) {
            float w = g_Wt[d * Dk + i];
#pragma unroll
            for (int r = 0; r < ST3; ++r) acc[r] = fmaf(Axs[r][d], w, acc[r]);
        }
        float bias = Wb[i];
#pragma unroll
        for (int r = 0; r < ST3; ++r) Gs[r][i] = acc[r] + bias;
    }
    __syncthreads();

    // per-row stats: warp w handles row w (8 of 10 warps)
    const int w = tid >> 5, lane = tid & 31;
    if (w < ST3) {
        float sum = 0.f, sq = 0.f;
        for (int c = lane; c < Dk; c += 32) {
            float v = Gs[w][c];
            sum += v;
            sq = fmaf(v, v, sq);
        }
#pragma unroll
        for (int o = 16; o > 0; o >>= 1) {
            sum += __shfl_xor_sync(0xffffffffu, sum, o);
            sq += __shfl_xor_sync(0xffffffffu, sq, o);
        }
        if (lane == 0) {
            float m = sum * (1.0f / Dk);
            float var = (sq - (float)Dk * m * m) * (1.0f / (Dk - 1));
            float sd = sqrtf(fmaxf(var, 0.f));
            mean_s[w] = m;
            inv_s[w] = 1.0f / (sd + 1e-6f);
        }
    }
    __syncthreads();

    if (i < Dk) {
        float a = lna[i], bb = lnb[i];
#pragma unroll
        for (int r = 0; r < ST3; ++r) {
            float v = a * (Gs[r][i] - mean_s[r]) * inv_s[r] + bb;
            node[(size_t)(b * Sk + s0 + r) * Dk + i] = fmaxf(v, 0.f);
        }
    }
}

// ---------------------------------------------------------------------------
// K4: pa = node @ Wa^T ; pb = node @ Wb2^T  (Wa = W1[:, :D], Wb2 = W1[:, D:])
// grid (S/8, B), 128 threads (first 100 active: 50 for pa, 50 for pb)
// ---------------------------------------------------------------------------
#define ST4 8
__global__ __launch_bounds__(128) void k_pab(const float* __restrict__ node,
                                             const float* __restrict__ W1) {
    __shared__ float Ns[ST4][Dk];
    const int tid = threadIdx.x;
    const int s0 = blockIdx.x * ST4;
    const int b = blockIdx.y;

    for (int idx = tid; idx < ST4 * Dk; idx += 128) {
        int r = idx / Dk, c = idx - r * Dk;
        Ns[r][c] = node[(size_t)(b * Sk + s0 + r) * Dk + c];
    }
    __syncthreads();

    if (tid < 2 * DEPk) {
        const bool is_a = (tid < DEPk);
        const int k = is_a ? tid : tid - DEPk;
        const float* wr = W1 + (size_t)k * (2 * Dk) + (is_a ? 0 : Dk);
        float acc[ST4];
#pragma unroll
        for (int r = 0; r < ST4; ++r) acc[r] = 0.f;
        for (int d = 0; d < Dk; ++d) {
            float w = wr[d];
#pragma unroll
            for (int r = 0; r < ST4; ++r) acc[r] = fmaf(Ns[r][d], w, acc[r]);
        }
        float* o = is_a ? g_pa : g_pb;
#pragma unroll
        for (int r = 0; r < ST4; ++r)
            o[(size_t)(b * Sk + s0 + r) * DEPk + k] = acc[r];
    }
}

// ---------------------------------------------------------------------------
// K5: edge[b,i,j,k] = pa[b,j,k] + pb[b,i,k] + W1_b[k]
// grid (S, B), 256 threads; float2 stores
// ---------------------------------------------------------------------------
__global__ __launch_bounds__(256) void k_edge(const float* __restrict__ W1b,
                                              float* __restrict__ edge) {
    __shared__ float pbb[DEPk];
    const int tid = threadIdx.x;
    const int i = blockIdx.x;
    const int b = blockIdx.y;

    if (tid < DEPk)
        pbb[tid] = g_pb[(size_t)(b * Sk + i) * DEPk + tid] + W1b[tid];
    __syncthreads();

    const float2* par = reinterpret_cast<const float2*>(g_pa + (size_t)b * Sk * DEPk);
    float2* er = reinterpret_cast<float2*>(edge + (size_t)(b * Sk + i) * Sk * DEPk);

    for (int idx = tid; idx < (Sk * DEPk) / 2; idx += 256) {
        int e0 = 2 * idx;
        int k = e0 % DEPk;  // DEPk even -> k, k+1 in same row
        float2 p = par[idx];
        p.x += pbb[k];
        p.y += pbb[k + 1];
        er[idx] = p;
    }
}

// ---------------------------------------------------------------------------
extern "C" void kernel_launch(void* const* d_in, const int* in_sizes, int n_in,
                              void* d_out, int out_size) {
    const float* wps = (const float*)d_in[0];   // (B,S,S,E)
    // d_in[1] = weight_adj (int64) — unused by the reference
    const float* x   = (const float*)d_in[2];   // (B,S,D)
    const float* sl  = (const float*)d_in[3];   // (B,E,S,S)
    const float* Ww  = (const float*)d_in[4];   // (D,D)
    const float* Wb  = (const float*)d_in[5];   // (D,)
    const float* lna = (const float*)d_in[6];   // (D,)
    const float* lnb = (const float*)d_in[7];   // (D,)
    const float* W1  = (const float*)d_in[8];   // (DEP, 2D)
    const float* W1b = (const float*)d_in[9];   // (DEP,)

    float* out = (float*)d_out;
    float* node = out;                              // (B,S,D)
    float* edge = out + (size_t)Bk * Sk * Dk;       // (B,S,S,DEP)

    k_abar<<<dim3(Sk, Bk), 128>>>(wps, sl);
    k_ax<<<dim3(Sk / ST2, Bk), 128>>>(x);
    k_wt<<<dim3(Dk), 320>>>(Ww);
    k_gemm_ln<<<dim3(Sk / ST3, Bk), 320>>>(Wb, lna, lnb, node);
    k_pab<<<dim3(Sk / ST4, Bk), 128>>>(node, W1);
    k_edge<<<dim3(Sk, Bk), 256>>>(W1b, edge);
}